// round 4
// baseline (speedup 1.0000x reference)
#include <cuda_runtime.h>
#include <math.h>
#include <stdint.h>

#define B_    2
#define H_    16
#define BH    32
#define T_    2048
#define S_    2048
#define D_    64
#define U_SEL 614        // max(int(min(0.4*ln(2048),1024)), int(0.3*2048)) = max(3,614)
#define SEL_STRIDE 640
#define SCALE 0.125f     // 1/sqrt(64)
#define LOGS  7.624618986159398  // log(2048)

__device__ float g_kl[BH * T_];
__device__ int   g_sel[BH * SEL_STRIDE];

// ---------------------------------------------------------------------------
// cp.async helpers (LDGSTS, 16B)
// ---------------------------------------------------------------------------
__device__ __forceinline__ uint32_t smem_u32(const void* p) {
    return (uint32_t)__cvta_generic_to_shared(p);
}
__device__ __forceinline__ void cp_async16(uint32_t dst, const void* src) {
    asm volatile("cp.async.cg.shared.global [%0], [%1], 16;\n" :: "r"(dst), "l"(src));
}
__device__ __forceinline__ void cp_commit() {
    asm volatile("cp.async.commit_group;\n");
}
template <int N>
__device__ __forceinline__ void cp_wait() {
    asm volatile("cp.async.wait_group %0;\n" :: "n"(N));
}

// ---------------------------------------------------------------------------
// Phase 1: KL score per query. 128q x 128k block tile, thread tile 8x8,
// 256 threads, K double-buffered via cp.async. All smem traffic LDS.128.
// K swizzle at 16B granularity: Ks4[c*16 + (dv ^ (c & 15))].
// d-accumulation order (ascending, x..w) identical to R3 -> scores bitwise
// identical -> selection unchanged.
// ---------------------------------------------------------------------------
__global__ __launch_bounds__(256, 1)
void kl_kernel(const float* __restrict__ q, const float* __restrict__ k)
{
    extern __shared__ float4 smem4[];
    float4* Qs4 = smem4;              // 128*16 = 2048 float4 (32KB)
    float4* Ks4 = smem4 + 2048;       // 2 buffers * 2048 float4 (64KB)

    const int tid = threadIdx.x;
    const int tx = tid & 15, ty = tid >> 4;
    const int bh = blockIdx.y;
    const int q0 = blockIdx.x * 128;

    const float4* qp4 = (const float4*)(q + ((size_t)bh * T_ + q0) * D_);
    const float4* kp4 = (const float4*)(k + (size_t)bh * S_ * D_);

    for (int lin = tid; lin < 2048; lin += 256)
        Qs4[lin] = qp4[lin];

    // prefetch K tile 0 into buffer 0 (swizzled)
    {
        const float4* ktp4 = kp4;
        for (int lin = tid; lin < 2048; lin += 256) {
            int r = lin >> 4, dv = lin & 15;
            cp_async16(smem_u32(&Ks4[(r << 4) + (dv ^ (r & 15))]), &ktp4[lin]);
        }
        cp_commit();
    }

    float  row_m[8];
    double row_Z[8], row_A[8];
#pragma unroll
    for (int i = 0; i < 8; i++) { row_m[i] = -1e30f; row_Z[i] = 0.0; row_A[i] = 0.0; }

    const int NT = S_ / 128;   // 16 tiles
    for (int kt = 0; kt < NT; kt++) {
        // prefetch next tile into the other buffer
        if (kt + 1 < NT) {
            const float4* ktp4 = kp4 + (size_t)(kt + 1) * 2048;
            float4* dst = Ks4 + ((kt + 1) & 1) * 2048;
            for (int lin = tid; lin < 2048; lin += 256) {
                int r = lin >> 4, dv = lin & 15;
                cp_async16(smem_u32(&dst[(r << 4) + (dv ^ (r & 15))]), &ktp4[lin]);
            }
            cp_commit();
            cp_wait<1>();
        } else {
            cp_wait<0>();
        }
        __syncthreads();

        const float4* Kb = Ks4 + (kt & 1) * 2048;

        float acc[8][8];
#pragma unroll
        for (int i = 0; i < 8; i++)
#pragma unroll
            for (int j = 0; j < 8; j++) acc[i][j] = 0.f;

#pragma unroll 2
        for (int dv = 0; dv < 16; dv++) {
            // (tx + 16j) & 15 == tx  ->  swizzled dv offset constant across j
            const float4* Kbase = Kb + (tx << 4) + (dv ^ tx);
            const float4* Qbase = Qs4 + ((8 * ty) << 4) + dv;
            float4 qv[8], kv[8];
#pragma unroll
            for (int i = 0; i < 8; i++) qv[i] = Qbase[i << 4];
#pragma unroll
            for (int j = 0; j < 8; j++) kv[j] = Kbase[j << 8];
#pragma unroll
            for (int i = 0; i < 8; i++)
#pragma unroll
                for (int j = 0; j < 8; j++) {
                    acc[i][j] = fmaf(qv[i].x, kv[j].x, acc[i][j]);
                    acc[i][j] = fmaf(qv[i].y, kv[j].y, acc[i][j]);
                    acc[i][j] = fmaf(qv[i].z, kv[j].z, acc[i][j]);
                    acc[i][j] = fmaf(qv[i].w, kv[j].w, acc[i][j]);
                }
        }

#pragma unroll
        for (int i = 0; i < 8; i++) {
            float tmax = -1e30f;
#pragma unroll
            for (int j = 0; j < 8; j++) {
                float s = fminf(fmaxf(acc[i][j] * SCALE, -50.f), 50.f);
                acc[i][j] = s;
                tmax = fmaxf(tmax, s);
            }
#pragma unroll
            for (int o = 8; o >= 1; o >>= 1)
                tmax = fmaxf(tmax, __shfl_xor_sync(0xffffffffu, tmax, o));

            float newm = fmaxf(row_m[i], tmax);
            float zt = 0.f, at = 0.f;
#pragma unroll
            for (int j = 0; j < 8; j++) {
                float p = acc[i][j] - newm;
                float e = __expf(p);
                zt += e;
                at = fmaf(e, p, at);
            }
#pragma unroll
            for (int o = 8; o >= 1; o >>= 1) {
                zt += __shfl_xor_sync(0xffffffffu, zt, o);
                at += __shfl_xor_sync(0xffffffffu, at, o);
            }
            float dm = row_m[i] - newm;
            float f  = __expf(dm);
            row_A[i] = (double)f * (row_A[i] + (double)dm * row_Z[i]) + (double)at;
            row_Z[i] = (double)f * row_Z[i] + (double)zt;
            row_m[i] = newm;
        }
        __syncthreads();   // all reads of Kb done before buffer reuse
    }

    if (tx == 0) {
#pragma unroll
        for (int i = 0; i < 8; i++) {
            double kl = row_A[i] / row_Z[i] - log(row_Z[i]) + LOGS;
            g_kl[bh * T_ + q0 + 8 * ty + i] = (float)kl;
        }
    }
}

// ---------------------------------------------------------------------------
// Phase 2: exact top-u via 8-bit MSB radix select, stable low-index tie-break.
// ---------------------------------------------------------------------------
__global__ void topk_kernel(int u)
{
    const int bh = blockIdx.x;
    const int tid = threadIdx.x;   // 256
    __shared__ unsigned keys[T_];
    __shared__ int hist[256];
    __shared__ int sums[256];
    __shared__ int sh_digit, sh_need;

    for (int t = tid; t < T_; t += 256) {
        unsigned b = __float_as_uint(g_kl[bh * T_ + t]);
        keys[t] = (b & 0x80000000u) ? ~b : (b | 0x80000000u);
    }
    __syncthreads();

    unsigned prefix = 0u, pmask = 0u;
    int need = u;
    for (int shift = 24; shift >= 0; shift -= 8) {
        hist[tid] = 0;
        __syncthreads();
        for (int t = tid; t < T_; t += 256) {
            unsigned kk = keys[t];
            if ((kk & pmask) == prefix)
                atomicAdd(&hist[(kk >> shift) & 255u], 1);
        }
        __syncthreads();
        if (tid == 0) {
            int cum = 0, d = 255;
            for (; d > 0; d--) {
                if (cum + hist[d] >= need) break;
                cum += hist[d];
            }
            sh_digit = d;
            sh_need  = need - cum;
        }
        __syncthreads();
        prefix |= ((unsigned)sh_digit) << shift;
        pmask  |= (255u << shift);
        need = sh_need;
        __syncthreads();
    }
    const unsigned thr = prefix;
    const int tie_take = need;

    const int base = tid * (T_ / 256);
    bool gtf[8], eqf[8];
    int cnt_eq = 0;
#pragma unroll
    for (int i = 0; i < 8; i++) {
        unsigned kk = keys[base + i];
        gtf[i] = (kk > thr);
        eqf[i] = (kk == thr);
        cnt_eq += eqf[i] ? 1 : 0;
    }
    sums[tid] = cnt_eq; __syncthreads();
    for (int off = 1; off < 256; off <<= 1) {
        int x = (tid >= off) ? sums[tid - off] : 0;
        __syncthreads();
        sums[tid] += x;
        __syncthreads();
    }
    int eqr = sums[tid] - cnt_eq;
    __syncthreads();

    bool self[8];
    int cnt_sel = 0;
#pragma unroll
    for (int i = 0; i < 8; i++) {
        bool s = gtf[i] || (eqf[i] && (eqr < tie_take));
        if (eqf[i]) eqr++;
        self[i] = s;
        cnt_sel += s ? 1 : 0;
    }
    sums[tid] = cnt_sel; __syncthreads();
    for (int off = 1; off < 256; off <<= 1) {
        int x = (tid >= off) ? sums[tid - off] : 0;
        __syncthreads();
        sums[tid] += x;
        __syncthreads();
    }
    int pos = sums[tid] - cnt_sel;
#pragma unroll
    for (int i = 0; i < 8; i++)
        if (self[i]) g_sel[bh * SEL_STRIDE + pos++] = base + i;
}

// ---------------------------------------------------------------------------
// Phase 3: sparse attention (unchanged from R3). 64q x 64k tiles, 4x4 thread
// tile with float4 O accumulators, 3 CTAs/SM -> 320 blocks in one wave.
// ---------------------------------------------------------------------------
__global__ __launch_bounds__(256, 3)
void attn_kernel(const float* __restrict__ q, const float* __restrict__ k,
                 const float* __restrict__ v, float* __restrict__ out, int u)
{
    __shared__ float4 Qs4[64 * 16];
    __shared__ float4 KP4[64 * 16];   // K (swizzled), then P (plain)
    __shared__ float4 Vs4[64 * 16];

    const int tid = threadIdx.x;
    const int tx = tid & 15, ty = tid >> 4;
    const int bh = blockIdx.y;
    const int q0 = blockIdx.x * 64;

    const int*    selp = g_sel + bh * SEL_STRIDE;
    const float4* kb4  = (const float4*)(k + (size_t)bh * S_ * D_);
    const float4* vb4  = (const float4*)(v + (size_t)bh * S_ * D_);
    const float4* qg4  = (const float4*)q;

    for (int lin = tid; lin < 64 * 16; lin += 256) {
        int r = lin >> 4, dv = lin & 15;
        int qi = q0 + r;
        float4 val = make_float4(0.f, 0.f, 0.f, 0.f);
        if (qi < u) val = qg4[((size_t)bh * T_ + selp[qi]) * 16 + dv];
        Qs4[lin] = val;
    }

    float row_m[4], row_Z[4];
    float4 O4[4];
#pragma unroll
    for (int i = 0; i < 4; i++) {
        row_m[i] = -1e30f; row_Z[i] = 0.f;
        O4[i] = make_float4(0.f, 0.f, 0.f, 0.f);
    }

    for (int kt = 0; kt < S_ / 64; kt++) {
        __syncthreads();
        const float4* kp4 = kb4 + (size_t)kt * 64 * 16;
        const float4* vp4 = vb4 + (size_t)kt * 64 * 16;
        for (int lin = tid; lin < 64 * 16; lin += 256) {
            int r = lin >> 4, dv = lin & 15;
            KP4[(r << 4) + (dv ^ (r & 15))] = kp4[lin];
            Vs4[lin] = vp4[lin];
        }
        __syncthreads();

        float acc[4][4];
#pragma unroll
        for (int i = 0; i < 4; i++)
#pragma unroll
            for (int j = 0; j < 4; j++) acc[i][j] = 0.f;

#pragma unroll 4
        for (int dv = 0; dv < 16; dv++) {
            float4 qv[4], kv[4];
#pragma unroll
            for (int i = 0; i < 4; i++) qv[i] = Qs4[((4 * ty + i) << 4) + dv];
#pragma unroll
            for (int j = 0; j < 4; j++) {
                int c = tx + 16 * j;
                kv[j] = KP4[(c << 4) + (dv ^ (c & 15))];
            }
#pragma unroll
            for (int i = 0; i < 4; i++)
#pragma unroll
                for (int j = 0; j < 4; j++) {
                    acc[i][j] = fmaf(qv[i].x, kv[j].x, acc[i][j]);
                    acc[i][j] = fmaf(qv[i].y, kv[j].y, acc[i][j]);
                    acc[i][j] = fmaf(qv[i].z, kv[j].z, acc[i][j]);
                    acc[i][j] = fmaf(qv[i].w, kv[j].w, acc[i][j]);
                }
        }

        float p[4][4];
#pragma unroll
        for (int i = 0; i < 4; i++) {
            float tmax = -1e30f;
#pragma unroll
            for (int j = 0; j < 4; j++) {
                float s = fminf(fmaxf(acc[i][j] * SCALE, -50.f), 50.f);
                acc[i][j] = s;
                tmax = fmaxf(tmax, s);
            }
#pragma unroll
            for (int o = 8; o >= 1; o >>= 1)
                tmax = fmaxf(tmax, __shfl_xor_sync(0xffffffffu, tmax, o));

            float newm = fmaxf(row_m[i], tmax);
            float f = __expf(row_m[i] - newm);
            float zt = 0.f;
#pragma unroll
            for (int j = 0; j < 4; j++) {
                float e = __expf(acc[i][j] - newm);
                p[i][j] = e;
                zt += e;
            }
#pragma unroll
            for (int o = 8; o >= 1; o >>= 1)
                zt += __shfl_xor_sync(0xffffffffu, zt, o);

            row_Z[i] = row_Z[i] * f + zt;
            O4[i].x *= f; O4[i].y *= f; O4[i].z *= f; O4[i].w *= f;
            row_m[i] = newm;
        }
        __syncthreads();   // done reading KP4 as K

        float* Pf = (float*)KP4;
#pragma unroll
        for (int i = 0; i < 4; i++)
#pragma unroll
            for (int j = 0; j < 4; j++)
                Pf[((4 * ty + i) << 6) + tx + 16 * j] = p[i][j];
        __syncthreads();

#pragma unroll 4
        for (int kkv = 0; kkv < 16; kkv++) {
            float4 pv[4], vv[4];
#pragma unroll
            for (int i = 0; i < 4; i++) pv[i] = KP4[((4 * ty + i) << 4) + kkv];
#pragma unroll
            for (int m = 0; m < 4; m++) vv[m] = Vs4[((4 * kkv + m) << 4) + tx];
#pragma unroll
            for (int i = 0; i < 4; i++) {
                O4[i].x = fmaf(pv[i].x, vv[0].x, O4[i].x);
                O4[i].y = fmaf(pv[i].x, vv[0].y, O4[i].y);
                O4[i].z = fmaf(pv[i].x, vv[0].z, O4[i].z);
                O4[i].w = fmaf(pv[i].x, vv[0].w, O4[i].w);
                O4[i].x = fmaf(pv[i].y, vv[1].x, O4[i].x);
                O4[i].y = fmaf(pv[i].y, vv[1].y, O4[i].y);
                O4[i].z = fmaf(pv[i].y, vv[1].z, O4[i].z);
                O4[i].w = fmaf(pv[i].y, vv[1].w, O4[i].w);
                O4[i].x = fmaf(pv[i].z, vv[2].x, O4[i].x);
                O4[i].y = fmaf(pv[i].z, vv[2].y, O4[i].y);
                O4[i].z = fmaf(pv[i].z, vv[2].z, O4[i].z);
                O4[i].w = fmaf(pv[i].z, vv[2].w, O4[i].w);
                O4[i].x = fmaf(pv[i].w, vv[3].x, O4[i].x);
                O4[i].y = fmaf(pv[i].w, vv[3].y, O4[i].y);
                O4[i].z = fmaf(pv[i].w, vv[3].z, O4[i].z);
                O4[i].w = fmaf(pv[i].w, vv[3].w, O4[i].w);
            }
        }
    }

#pragma unroll
    for (int i = 0; i < 4; i++) {
        int qi = q0 + 4 * ty + i;
        if (qi < u) {
            int t = selp[qi];
            float inv = 1.0f / row_Z[i];
            float4 o = make_float4(O4[i].x * inv, O4[i].y * inv,
                                   O4[i].z * inv, O4[i].w * inv);
            float4* op4 = (float4*)(out + ((size_t)bh * T_ + t) * D_);
            op4[tx] = o;
        }
    }
}

// ---------------------------------------------------------------------------
extern "C" void kernel_launch(void* const* d_in, const int* in_sizes, int n_in,
                              void* d_out, int out_size)
{
    (void)in_sizes; (void)n_in;
    const float* q = (const float*)d_in[0];
    const float* k = (const float*)d_in[1];
    const float* v = (const float*)d_in[2];
    float* out = (float*)d_out;

    const int kl_smem = (2048 + 2 * 2048) * 16;   // 96 KB
    cudaFuncSetAttribute(kl_kernel, cudaFuncAttributeMaxDynamicSharedMemorySize,
                         kl_smem);

    cudaMemsetAsync(d_out, 0, (size_t)out_size * sizeof(float), 0);

    dim3 g1(T_ / 128, BH);
    kl_kernel<<<g1, 256, kl_smem>>>(q, k);

    topk_kernel<<<BH, 256>>>(U_SEL);

    dim3 g3((U_SEL + 63) / 64, BH);
    attn_kernel<<<g3, 256>>>(q, k, v, out, U_SEL);
}

// round 5
// speedup vs baseline: 1.1619x; 1.1619x over previous
#include <cuda_runtime.h>
#include <math.h>
#include <stdint.h>

#define B_    2
#define H_    16
#define BH    32
#define T_    2048
#define S_    2048
#define D_    64
#define U_SEL 614        // max(int(min(0.4*ln(2048),1024)), int(0.3*2048)) = max(3,614)
#define SEL_STRIDE 640
#define SCALE 0.125f     // 1/sqrt(64)
#define LOGS  7.624618986159398  // log(2048)
#define SHALF 1024       // S per split half

__device__ int    g_sel[BH * SEL_STRIDE];
__device__ float  g_m[2 * BH * T_];
__device__ double g_Zd[2 * BH * T_];
__device__ double g_Ad[2 * BH * T_];

// ---------------------------------------------------------------------------
// cp.async helpers
// ---------------------------------------------------------------------------
__device__ __forceinline__ uint32_t smem_u32(const void* p) {
    return (uint32_t)__cvta_generic_to_shared(p);
}
__device__ __forceinline__ void cp_async16(uint32_t dst, const void* src) {
    asm volatile("cp.async.cg.shared.global [%0], [%1], 16;\n" :: "r"(dst), "l"(src));
}
__device__ __forceinline__ void cp_commit() {
    asm volatile("cp.async.commit_group;\n");
}
template <int N>
__device__ __forceinline__ void cp_wait() {
    asm volatile("cp.async.wait_group %0;\n" :: "n"(N));
}

// ---------------------------------------------------------------------------
// Phase 1: partial online-softmax KL stats. 128q x 128k tile, 8x8 thread
// tile, 2 CTAs/SM, K double-buffered cp.async, S split in 2 halves (merged
// in topk). Z/A accumulators are DOUBLES IN SMEM (updated by tx==0 lane)
// -> register count stays under 128. Score dv-order identical to R3.
// ---------------------------------------------------------------------------
__global__ __launch_bounds__(256, 2)
void kl_kernel(const float* __restrict__ q, const float* __restrict__ k)
{
    extern __shared__ float4 smem4[];
    float4* Qs4 = smem4;               // 2048 float4 (32KB)
    float4* Ks4 = smem4 + 2048;        // 2 * 2048 float4 (64KB)
    double* Zs  = (double*)(smem4 + 2048 + 4096);   // 128 doubles
    double* As  = Zs + 128;                          // 128 doubles

    const int tid = threadIdx.x;
    const int tx = tid & 15, ty = tid >> 4;
    const int bh = blockIdx.y;
    const int q0 = blockIdx.x * 128;
    const int sh = blockIdx.z;

    const float4* qp4 = (const float4*)(q + ((size_t)bh * T_ + q0) * D_);
    const float4* kp4 = (const float4*)(k + ((size_t)bh * S_ + sh * SHALF) * D_);

    for (int lin = tid; lin < 2048; lin += 256)
        Qs4[lin] = qp4[lin];
    if (tid < 128) { Zs[tid] = 0.0; As[tid] = 0.0; }

    // prefetch K tile 0 into buffer 0 (swizzled at 16B granularity)
    for (int lin = tid; lin < 2048; lin += 256) {
        int r = lin >> 4, dv = lin & 15;
        cp_async16(smem_u32(&Ks4[(r << 4) + (dv ^ (r & 15))]), &kp4[lin]);
    }
    cp_commit();

    float row_m[8];
#pragma unroll
    for (int i = 0; i < 8; i++) row_m[i] = -1e30f;

    const int NT = SHALF / 128;   // 8 tiles
    for (int kt = 0; kt < NT; kt++) {
        if (kt + 1 < NT) {
            const float4* ktp4 = kp4 + (size_t)(kt + 1) * 2048;
            float4* dst = Ks4 + ((kt + 1) & 1) * 2048;
            for (int lin = tid; lin < 2048; lin += 256) {
                int r = lin >> 4, dv = lin & 15;
                cp_async16(smem_u32(&dst[(r << 4) + (dv ^ (r & 15))]), &ktp4[lin]);
            }
            cp_commit();
            cp_wait<1>();
        } else {
            cp_wait<0>();
        }
        __syncthreads();

        const float4* Kb = Ks4 + (kt & 1) * 2048;

        float acc[8][8];
#pragma unroll
        for (int i = 0; i < 8; i++)
#pragma unroll
            for (int j = 0; j < 8; j++) acc[i][j] = 0.f;

#pragma unroll 4
        for (int dv = 0; dv < 16; dv++) {
            // (tx + 16j) & 15 == tx -> swizzled dv offset constant across j
            const float4* Kbase = Kb + (tx << 4) + (dv ^ tx);
            const float4* Qbase = Qs4 + ((8 * ty) << 4) + dv;
            float4 qv[8], kv[8];
#pragma unroll
            for (int i = 0; i < 8; i++) qv[i] = Qbase[i << 4];
#pragma unroll
            for (int j = 0; j < 8; j++) kv[j] = Kbase[j << 8];
#pragma unroll
            for (int i = 0; i < 8; i++)
#pragma unroll
                for (int j = 0; j < 8; j++) {
                    acc[i][j] = fmaf(qv[i].x, kv[j].x, acc[i][j]);
                    acc[i][j] = fmaf(qv[i].y, kv[j].y, acc[i][j]);
                    acc[i][j] = fmaf(qv[i].z, kv[j].z, acc[i][j]);
                    acc[i][j] = fmaf(qv[i].w, kv[j].w, acc[i][j]);
                }
        }

#pragma unroll
        for (int i = 0; i < 8; i++) {
            const int r = 8 * ty + i;
            float tmax = -1e30f;
#pragma unroll
            for (int j = 0; j < 8; j++) {
                float s = fminf(fmaxf(acc[i][j] * SCALE, -50.f), 50.f);
                acc[i][j] = s;
                tmax = fmaxf(tmax, s);
            }
#pragma unroll
            for (int o = 8; o >= 1; o >>= 1)
                tmax = fmaxf(tmax, __shfl_xor_sync(0xffffffffu, tmax, o));

            float newm = fmaxf(row_m[i], tmax);
            float zt = 0.f, at = 0.f;
#pragma unroll
            for (int j = 0; j < 8; j++) {
                float p = acc[i][j] - newm;
                float e = __expf(p);
                zt += e;
                at = fmaf(e, p, at);
            }
#pragma unroll
            for (int o = 8; o >= 1; o >>= 1) {
                zt += __shfl_xor_sync(0xffffffffu, zt, o);
                at += __shfl_xor_sync(0xffffffffu, at, o);
            }
            float dm = row_m[i] - newm;
            if (tx == 0) {
                double f = (double)__expf(dm);
                double Zold = Zs[r], Aold = As[r];
                Zs[r] = f * Zold + (double)zt;
                As[r] = f * (Aold + (double)dm * Zold) + (double)at;
            }
            row_m[i] = newm;
        }
        __syncthreads();   // all reads of Kb done before buffer reuse
    }

    if (tx == 0) {
#pragma unroll
        for (int i = 0; i < 8; i++) {
            const int r = 8 * ty + i;
            size_t idx = (size_t)sh * (BH * T_) + (size_t)bh * T_ + q0 + r;
            g_m[idx]  = row_m[i];
            g_Zd[idx] = Zs[r];
            g_Ad[idx] = As[r];
        }
    }
}

// ---------------------------------------------------------------------------
// Phase 2: merge S-halves (exact double online-softmax merge), compute KL,
// then exact top-u via 8-bit MSB radix select, stable low-index tie-break.
// ---------------------------------------------------------------------------
__global__ void topk_kernel(int u)
{
    const int bh = blockIdx.x;
    const int tid = threadIdx.x;   // 256
    __shared__ unsigned keys[T_];
    __shared__ int hist[256];
    __shared__ int sums[256];
    __shared__ int sh_digit, sh_need;

    for (int t = tid; t < T_; t += 256) {
        size_t i0 = (size_t)bh * T_ + t;
        size_t i1 = (size_t)BH * T_ + i0;
        double m0 = (double)g_m[i0], m1 = (double)g_m[i1];
        double m = fmax(m0, m1);
        double e0 = exp(m0 - m), e1 = exp(m1 - m);
        double Z0 = g_Zd[i0], Z1 = g_Zd[i1];
        double Z = e0 * Z0 + e1 * Z1;
        double A = e0 * (g_Ad[i0] + (m0 - m) * Z0)
                 + e1 * (g_Ad[i1] + (m1 - m) * Z1);
        float klf = (float)(A / Z - log(Z) + LOGS);
        unsigned b = __float_as_uint(klf);
        keys[t] = (b & 0x80000000u) ? ~b : (b | 0x80000000u);
    }
    __syncthreads();

    unsigned prefix = 0u, pmask = 0u;
    int need = u;
    for (int shift = 24; shift >= 0; shift -= 8) {
        hist[tid] = 0;
        __syncthreads();
        for (int t = tid; t < T_; t += 256) {
            unsigned kk = keys[t];
            if ((kk & pmask) == prefix)
                atomicAdd(&hist[(kk >> shift) & 255u], 1);
        }
        __syncthreads();
        if (tid == 0) {
            int cum = 0, d = 255;
            for (; d > 0; d--) {
                if (cum + hist[d] >= need) break;
                cum += hist[d];
            }
            sh_digit = d;
            sh_need  = need - cum;
        }
        __syncthreads();
        prefix |= ((unsigned)sh_digit) << shift;
        pmask  |= (255u << shift);
        need = sh_need;
        __syncthreads();
    }
    const unsigned thr = prefix;
    const int tie_take = need;

    const int base = tid * (T_ / 256);
    bool gtf[8], eqf[8];
    int cnt_eq = 0;
#pragma unroll
    for (int i = 0; i < 8; i++) {
        unsigned kk = keys[base + i];
        gtf[i] = (kk > thr);
        eqf[i] = (kk == thr);
        cnt_eq += eqf[i] ? 1 : 0;
    }
    sums[tid] = cnt_eq; __syncthreads();
    for (int off = 1; off < 256; off <<= 1) {
        int x = (tid >= off) ? sums[tid - off] : 0;
        __syncthreads();
        sums[tid] += x;
        __syncthreads();
    }
    int eqr = sums[tid] - cnt_eq;
    __syncthreads();

    bool self[8];
    int cnt_sel = 0;
#pragma unroll
    for (int i = 0; i < 8; i++) {
        bool s = gtf[i] || (eqf[i] && (eqr < tie_take));
        if (eqf[i]) eqr++;
        self[i] = s;
        cnt_sel += s ? 1 : 0;
    }
    sums[tid] = cnt_sel; __syncthreads();
    for (int off = 1; off < 256; off <<= 1) {
        int x = (tid >= off) ? sums[tid - off] : 0;
        __syncthreads();
        sums[tid] += x;
        __syncthreads();
    }
    int pos = sums[tid] - cnt_sel;
#pragma unroll
    for (int i = 0; i < 8; i++)
        if (self[i]) g_sel[bh * SEL_STRIDE + pos++] = base + i;
}

// ---------------------------------------------------------------------------
// Phase 3: sparse attention (unchanged, proven). 64q x 64k tiles, 4x4 thread
// tile with float4 O accumulators, 3 CTAs/SM -> 320 blocks in one wave.
// ---------------------------------------------------------------------------
__global__ __launch_bounds__(256, 3)
void attn_kernel(const float* __restrict__ q, const float* __restrict__ k,
                 const float* __restrict__ v, float* __restrict__ out, int u)
{
    __shared__ float4 Qs4[64 * 16];
    __shared__ float4 KP4[64 * 16];   // K (swizzled), then P (plain)
    __shared__ float4 Vs4[64 * 16];

    const int tid = threadIdx.x;
    const int tx = tid & 15, ty = tid >> 4;
    const int bh = blockIdx.y;
    const int q0 = blockIdx.x * 64;

    const int*    selp = g_sel + bh * SEL_STRIDE;
    const float4* kb4  = (const float4*)(k + (size_t)bh * S_ * D_);
    const float4* vb4  = (const float4*)(v + (size_t)bh * S_ * D_);
    const float4* qg4  = (const float4*)q;

    for (int lin = tid; lin < 64 * 16; lin += 256) {
        int r = lin >> 4, dv = lin & 15;
        int qi = q0 + r;
        float4 val = make_float4(0.f, 0.f, 0.f, 0.f);
        if (qi < u) val = qg4[((size_t)bh * T_ + selp[qi]) * 16 + dv];
        Qs4[lin] = val;
    }

    float row_m[4], row_Z[4];
    float4 O4[4];
#pragma unroll
    for (int i = 0; i < 4; i++) {
        row_m[i] = -1e30f; row_Z[i] = 0.f;
        O4[i] = make_float4(0.f, 0.f, 0.f, 0.f);
    }

    for (int kt = 0; kt < S_ / 64; kt++) {
        __syncthreads();
        const float4* kp4 = kb4 + (size_t)kt * 64 * 16;
        const float4* vp4 = vb4 + (size_t)kt * 64 * 16;
        for (int lin = tid; lin < 64 * 16; lin += 256) {
            int r = lin >> 4, dv = lin & 15;
            KP4[(r << 4) + (dv ^ (r & 15))] = kp4[lin];
            Vs4[lin] = vp4[lin];
        }
        __syncthreads();

        float acc[4][4];
#pragma unroll
        for (int i = 0; i < 4; i++)
#pragma unroll
            for (int j = 0; j < 4; j++) acc[i][j] = 0.f;

#pragma unroll 4
        for (int dv = 0; dv < 16; dv++) {
            float4 qv[4], kv[4];
#pragma unroll
            for (int i = 0; i < 4; i++) qv[i] = Qs4[((4 * ty + i) << 4) + dv];
#pragma unroll
            for (int j = 0; j < 4; j++) {
                int c = tx + 16 * j;
                kv[j] = KP4[(c << 4) + (dv ^ (c & 15))];
            }
#pragma unroll
            for (int i = 0; i < 4; i++)
#pragma unroll
                for (int j = 0; j < 4; j++) {
                    acc[i][j] = fmaf(qv[i].x, kv[j].x, acc[i][j]);
                    acc[i][j] = fmaf(qv[i].y, kv[j].y, acc[i][j]);
                    acc[i][j] = fmaf(qv[i].z, kv[j].z, acc[i][j]);
                    acc[i][j] = fmaf(qv[i].w, kv[j].w, acc[i][j]);
                }
        }

        float p[4][4];
#pragma unroll
        for (int i = 0; i < 4; i++) {
            float tmax = -1e30f;
#pragma unroll
            for (int j = 0; j < 4; j++) {
                float s = fminf(fmaxf(acc[i][j] * SCALE, -50.f), 50.f);
                acc[i][j] = s;
                tmax = fmaxf(tmax, s);
            }
#pragma unroll
            for (int o = 8; o >= 1; o >>= 1)
                tmax = fmaxf(tmax, __shfl_xor_sync(0xffffffffu, tmax, o));

            float newm = fmaxf(row_m[i], tmax);
            float f = __expf(row_m[i] - newm);
            float zt = 0.f;
#pragma unroll
            for (int j = 0; j < 4; j++) {
                float e = __expf(acc[i][j] - newm);
                p[i][j] = e;
                zt += e;
            }
#pragma unroll
            for (int o = 8; o >= 1; o >>= 1)
                zt += __shfl_xor_sync(0xffffffffu, zt, o);

            row_Z[i] = row_Z[i] * f + zt;
            O4[i].x *= f; O4[i].y *= f; O4[i].z *= f; O4[i].w *= f;
            row_m[i] = newm;
        }
        __syncthreads();   // done reading KP4 as K

        float* Pf = (float*)KP4;
#pragma unroll
        for (int i = 0; i < 4; i++)
#pragma unroll
            for (int j = 0; j < 4; j++)
                Pf[((4 * ty + i) << 6) + tx + 16 * j] = p[i][j];
        __syncthreads();

#pragma unroll 4
        for (int kkv = 0; kkv < 16; kkv++) {
            float4 pv[4], vv[4];
#pragma unroll
            for (int i = 0; i < 4; i++) pv[i] = KP4[((4 * ty + i) << 4) + kkv];
#pragma unroll
            for (int m = 0; m < 4; m++) vv[m] = Vs4[((4 * kkv + m) << 4) + tx];
#pragma unroll
            for (int i = 0; i < 4; i++) {
                O4[i].x = fmaf(pv[i].x, vv[0].x, O4[i].x);
                O4[i].y = fmaf(pv[i].x, vv[0].y, O4[i].y);
                O4[i].z = fmaf(pv[i].x, vv[0].z, O4[i].z);
                O4[i].w = fmaf(pv[i].x, vv[0].w, O4[i].w);
                O4[i].x = fmaf(pv[i].y, vv[1].x, O4[i].x);
                O4[i].y = fmaf(pv[i].y, vv[1].y, O4[i].y);
                O4[i].z = fmaf(pv[i].y, vv[1].z, O4[i].z);
                O4[i].w = fmaf(pv[i].y, vv[1].w, O4[i].w);
                O4[i].x = fmaf(pv[i].z, vv[2].x, O4[i].x);
                O4[i].y = fmaf(pv[i].z, vv[2].y, O4[i].y);
                O4[i].z = fmaf(pv[i].z, vv[2].z, O4[i].z);
                O4[i].w = fmaf(pv[i].z, vv[2].w, O4[i].w);
                O4[i].x = fmaf(pv[i].w, vv[3].x, O4[i].x);
                O4[i].y = fmaf(pv[i].w, vv[3].y, O4[i].y);
                O4[i].z = fmaf(pv[i].w, vv[3].z, O4[i].z);
                O4[i].w = fmaf(pv[i].w, vv[3].w, O4[i].w);
            }
        }
    }

#pragma unroll
    for (int i = 0; i < 4; i++) {
        int qi = q0 + 4 * ty + i;
        if (qi < u) {
            int t = selp[qi];
            float inv = 1.0f / row_Z[i];
            float4 o = make_float4(O4[i].x * inv, O4[i].y * inv,
                                   O4[i].z * inv, O4[i].w * inv);
            float4* op4 = (float4*)(out + ((size_t)bh * T_ + t) * D_);
            op4[tx] = o;
        }
    }
}

// ---------------------------------------------------------------------------
extern "C" void kernel_launch(void* const* d_in, const int* in_sizes, int n_in,
                              void* d_out, int out_size)
{
    (void)in_sizes; (void)n_in;
    const float* q = (const float*)d_in[0];
    const float* k = (const float*)d_in[1];
    const float* v = (const float*)d_in[2];
    float* out = (float*)d_out;

    // Q(32K) + 2x K(32K) + 256 doubles(2K) = 98304 + 2048
    const int kl_smem = (2048 + 2 * 2048) * 16 + 256 * 8;
    cudaFuncSetAttribute(kl_kernel, cudaFuncAttributeMaxDynamicSharedMemorySize,
                         kl_smem);

    cudaMemsetAsync(d_out, 0, (size_t)out_size * sizeof(float), 0);

    dim3 g1(T_ / 128, BH, 2);
    kl_kernel<<<g1, 256, kl_smem>>>(q, k);

    topk_kernel<<<BH, 256>>>(U_SEL);

    dim3 g3((U_SEL + 63) / 64, BH);
    attn_kernel<<<g3, 256>>>(q, k, v, out, U_SEL);
}

// round 6
// speedup vs baseline: 1.2734x; 1.0959x over previous
#include <cuda_runtime.h>
#include <math.h>
#include <stdint.h>

#define B_    2
#define H_    16
#define BH    32
#define T_    2048
#define S_    2048
#define D_    64
#define U_SEL 614        // max(int(min(0.4*ln(2048),1024)), int(0.3*2048)) = max(3,614)
#define SEL_STRIDE 640
#define SCALE 0.125f     // 1/sqrt(64)
#define LOGS  7.624618986159398  // log(2048)
#define SHALF 1024       // S per split half
#define QSTRIDE 132      // Qt row stride (floats), multiple of 4
#define QSTRIDE_A 68     // attn Qt stride

__device__ int    g_sel[BH * SEL_STRIDE];
__device__ float  g_m[2 * BH * T_];
__device__ double g_Zd[2 * BH * T_];
__device__ double g_Ad[2 * BH * T_];

// ---------------------------------------------------------------------------
// helpers
// ---------------------------------------------------------------------------
__device__ __forceinline__ uint32_t smem_u32(const void* p) {
    return (uint32_t)__cvta_generic_to_shared(p);
}
__device__ __forceinline__ void cp_async16(uint32_t dst, const void* src) {
    asm volatile("cp.async.cg.shared.global [%0], [%1], 16;\n" :: "r"(dst), "l"(src));
}
__device__ __forceinline__ void cp_commit() {
    asm volatile("cp.async.commit_group;\n");
}
template <int N>
__device__ __forceinline__ void cp_wait() {
    asm volatile("cp.async.wait_group %0;\n" :: "n"(N));
}

// packed f32x2 ops (Blackwell): 2 fp32 FMAs per issue slot
__device__ __forceinline__ unsigned long long pack2(float lo, float hi) {
    unsigned long long r;
    asm("mov.b64 %0, {%1, %2};" : "=l"(r) : "f"(lo), "f"(hi));
    return r;
}
__device__ __forceinline__ void ffma2(unsigned long long& d,
                                      unsigned long long a, unsigned long long b) {
    asm("fma.rn.f32x2 %0, %1, %2, %3;" : "=l"(d) : "l"(a), "l"(b), "l"(d));
}
__device__ __forceinline__ float2 unpack2(unsigned long long a) {
    float lo, hi;
    asm("mov.b64 {%0, %1}, %2;" : "=f"(lo), "=f"(hi) : "l"(a));
    return make_float2(lo, hi);
}

// ---------------------------------------------------------------------------
// Phase 1: partial online-softmax KL stats. 128q x 128k tile, 8 rows x 8 cols
// per thread, rows packed in f32x2 pairs (acc2[4][8] u64). Q transposed in
// smem (Qt[d][row]); K double-buffered cp.async, swizzled. Per-row d-order
// unchanged -> per-row scores bitwise identical to R5 -> selection unchanged.
// ---------------------------------------------------------------------------
__global__ __launch_bounds__(256, 2)
void kl_kernel(const float* __restrict__ q, const float* __restrict__ k)
{
    extern __shared__ char smemraw[];
    float*  Qt  = (float*)smemraw;                        // 64*132 floats (33792 B)
    float4* Ks4 = (float4*)(smemraw + 64 * QSTRIDE * 4);  // 2*2048 float4 (64 KB)
    double* Zs  = (double*)(smemraw + 64 * QSTRIDE * 4 + 2 * 2048 * 16);
    double* As  = Zs + 128;

    const int tid = threadIdx.x;
    const int tx = tid & 15, ty = tid >> 4;
    const int bh = blockIdx.y;
    const int q0 = blockIdx.x * 128;
    const int sh = blockIdx.z;

    const float4* qp4 = (const float4*)(q + ((size_t)bh * T_ + q0) * D_);
    const float4* kp4 = (const float4*)(k + ((size_t)bh * S_ + sh * SHALF) * D_);

    // transpose Q into Qt[d][row]
    for (int lin = tid; lin < 2048; lin += 256) {
        int row = lin >> 4, dv = lin & 15;
        float4 vq = qp4[lin];
        float* dst = Qt + (4 * dv) * QSTRIDE + row;
        dst[0 * QSTRIDE] = vq.x;
        dst[1 * QSTRIDE] = vq.y;
        dst[2 * QSTRIDE] = vq.z;
        dst[3 * QSTRIDE] = vq.w;
    }
    if (tid < 128) { Zs[tid] = 0.0; As[tid] = 0.0; }

    // prefetch K tile 0 (swizzled at 16B granularity)
    for (int lin = tid; lin < 2048; lin += 256) {
        int r = lin >> 4, dv = lin & 15;
        cp_async16(smem_u32(&Ks4[(r << 4) + (dv ^ (r & 15))]), &kp4[lin]);
    }
    cp_commit();

    float row_m[8];
#pragma unroll
    for (int i = 0; i < 8; i++) row_m[i] = -1e30f;

    const int NT = SHALF / 128;   // 8 tiles
    for (int kt = 0; kt < NT; kt++) {
        if (kt + 1 < NT) {
            const float4* ktp4 = kp4 + (size_t)(kt + 1) * 2048;
            float4* dst = Ks4 + ((kt + 1) & 1) * 2048;
            for (int lin = tid; lin < 2048; lin += 256) {
                int r = lin >> 4, dv = lin & 15;
                cp_async16(smem_u32(&dst[(r << 4) + (dv ^ (r & 15))]), &ktp4[lin]);
            }
            cp_commit();
            cp_wait<1>();
        } else {
            cp_wait<0>();
        }
        __syncthreads();

        const float4* Kb = Ks4 + (kt & 1) * 2048;

        unsigned long long acc2[4][8];   // row-pairs (8ty+2p, 8ty+2p+1) x 8 cols
#pragma unroll
        for (int p = 0; p < 4; p++)
#pragma unroll
            for (int j = 0; j < 8; j++) acc2[p][j] = 0ULL;

#pragma unroll 4
        for (int dv = 0; dv < 16; dv++) {
            const float4* Kbase = Kb + (tx << 4) + (dv ^ tx);
            float4 kv[8];
#pragma unroll
            for (int j = 0; j < 8; j++) kv[j] = Kbase[j << 8];

            const float* Qb = Qt + (4 * dv) * QSTRIDE + 8 * ty;
#pragma unroll
            for (int dsub = 0; dsub < 4; dsub++) {
                float4 qa = *(const float4*)(Qb + dsub * QSTRIDE);
                float4 qb = *(const float4*)(Qb + dsub * QSTRIDE + 4);
                unsigned long long q01 = pack2(qa.x, qa.y);
                unsigned long long q23 = pack2(qa.z, qa.w);
                unsigned long long q45 = pack2(qb.x, qb.y);
                unsigned long long q67 = pack2(qb.z, qb.w);
#pragma unroll
                for (int j = 0; j < 8; j++) {
                    float ks = ((const float*)&kv[j])[dsub];
                    unsigned long long kb2 = pack2(ks, ks);
                    ffma2(acc2[0][j], q01, kb2);
                    ffma2(acc2[1][j], q23, kb2);
                    ffma2(acc2[2][j], q45, kb2);
                    ffma2(acc2[3][j], q67, kb2);
                }
            }
        }

#pragma unroll
        for (int i = 0; i < 8; i++) {
            const int p = i >> 1;
            const int r = 8 * ty + i;
            float sv[8];
#pragma unroll
            for (int j = 0; j < 8; j++) {
                float2 u = unpack2(acc2[p][j]);
                sv[j] = (i & 1) ? u.y : u.x;
            }
            float tmax = -1e30f;
#pragma unroll
            for (int j = 0; j < 8; j++) {
                float s = fminf(fmaxf(sv[j] * SCALE, -50.f), 50.f);
                sv[j] = s;
                tmax = fmaxf(tmax, s);
            }
#pragma unroll
            for (int o = 8; o >= 1; o >>= 1)
                tmax = fmaxf(tmax, __shfl_xor_sync(0xffffffffu, tmax, o));

            float newm = fmaxf(row_m[i], tmax);
            float zt = 0.f, at = 0.f;
#pragma unroll
            for (int j = 0; j < 8; j++) {
                float pp = sv[j] - newm;
                float e = __expf(pp);
                zt += e;
                at = fmaf(e, pp, at);
            }
#pragma unroll
            for (int o = 8; o >= 1; o >>= 1) {
                zt += __shfl_xor_sync(0xffffffffu, zt, o);
                at += __shfl_xor_sync(0xffffffffu, at, o);
            }
            float dm = row_m[i] - newm;
            if (tx == 0) {
                double f = (double)__expf(dm);
                double Zold = Zs[r], Aold = As[r];
                Zs[r] = f * Zold + (double)zt;
                As[r] = f * (Aold + (double)dm * Zold) + (double)at;
            }
            row_m[i] = newm;
        }
        __syncthreads();
    }

    if (tx == 0) {
#pragma unroll
        for (int i = 0; i < 8; i++) {
            const int r = 8 * ty + i;
            size_t idx = (size_t)sh * (BH * T_) + (size_t)bh * T_ + q0 + r;
            g_m[idx]  = row_m[i];
            g_Zd[idx] = Zs[r];
            g_Ad[idx] = As[r];
        }
    }
}

// ---------------------------------------------------------------------------
// Phase 2: merge halves (exact double merge), KL, exact top-u radix select.
// ---------------------------------------------------------------------------
__global__ void topk_kernel(int u)
{
    const int bh = blockIdx.x;
    const int tid = threadIdx.x;   // 256
    __shared__ unsigned keys[T_];
    __shared__ int hist[256];
    __shared__ int sums[256];
    __shared__ int sh_digit, sh_need;

    for (int t = tid; t < T_; t += 256) {
        size_t i0 = (size_t)bh * T_ + t;
        size_t i1 = (size_t)BH * T_ + i0;
        double m0 = (double)g_m[i0], m1 = (double)g_m[i1];
        double m = fmax(m0, m1);
        double e0 = exp(m0 - m), e1 = exp(m1 - m);
        double Z0 = g_Zd[i0], Z1 = g_Zd[i1];
        double Z = e0 * Z0 + e1 * Z1;
        double A = e0 * (g_Ad[i0] + (m0 - m) * Z0)
                 + e1 * (g_Ad[i1] + (m1 - m) * Z1);
        float klf = (float)(A / Z - log(Z) + LOGS);
        unsigned b = __float_as_uint(klf);
        keys[t] = (b & 0x80000000u) ? ~b : (b | 0x80000000u);
    }
    __syncthreads();

    unsigned prefix = 0u, pmask = 0u;
    int need = u;
    for (int shift = 24; shift >= 0; shift -= 8) {
        hist[tid] = 0;
        __syncthreads();
        for (int t = tid; t < T_; t += 256) {
            unsigned kk = keys[t];
            if ((kk & pmask) == prefix)
                atomicAdd(&hist[(kk >> shift) & 255u], 1);
        }
        __syncthreads();
        if (tid == 0) {
            int cum = 0, d = 255;
            for (; d > 0; d--) {
                if (cum + hist[d] >= need) break;
                cum += hist[d];
            }
            sh_digit = d;
            sh_need  = need - cum;
        }
        __syncthreads();
        prefix |= ((unsigned)sh_digit) << shift;
        pmask  |= (255u << shift);
        need = sh_need;
        __syncthreads();
    }
    const unsigned thr = prefix;
    const int tie_take = need;

    const int base = tid * (T_ / 256);
    bool gtf[8], eqf[8];
    int cnt_eq = 0;
#pragma unroll
    for (int i = 0; i < 8; i++) {
        unsigned kk = keys[base + i];
        gtf[i] = (kk > thr);
        eqf[i] = (kk == thr);
        cnt_eq += eqf[i] ? 1 : 0;
    }
    sums[tid] = cnt_eq; __syncthreads();
    for (int off = 1; off < 256; off <<= 1) {
        int x = (tid >= off) ? sums[tid - off] : 0;
        __syncthreads();
        sums[tid] += x;
        __syncthreads();
    }
    int eqr = sums[tid] - cnt_eq;
    __syncthreads();

    bool self[8];
    int cnt_sel = 0;
#pragma unroll
    for (int i = 0; i < 8; i++) {
        bool s = gtf[i] || (eqf[i] && (eqr < tie_take));
        if (eqf[i]) eqr++;
        self[i] = s;
        cnt_sel += s ? 1 : 0;
    }
    sums[tid] = cnt_sel; __syncthreads();
    for (int off = 1; off < 256; off <<= 1) {
        int x = (tid >= off) ? sums[tid - off] : 0;
        __syncthreads();
        sums[tid] += x;
        __syncthreads();
    }
    int pos = sums[tid] - cnt_sel;
#pragma unroll
    for (int i = 0; i < 8; i++)
        if (self[i]) g_sel[bh * SEL_STRIDE + pos++] = base + i;
}

// ---------------------------------------------------------------------------
// Phase 3: sparse attention. 64q x 64k tiles, 4 rows x 4 cols per thread.
// QK: row-pair FFMA2 via transposed gathered Q. PV: output-pair FFMA2.
// ---------------------------------------------------------------------------
__global__ __launch_bounds__(256, 3)
void attn_kernel(const float* __restrict__ q, const float* __restrict__ k,
                 const float* __restrict__ v, float* __restrict__ out, int u)
{
    extern __shared__ char smemraw[];
    float*  Qt  = (float*)smemraw;                          // 64*68 floats (17408 B)
    float4* KP4 = (float4*)(smemraw + 64 * QSTRIDE_A * 4);  // 1024 float4 (16 KB)
    float4* Vs4 = KP4 + 1024;                               // 1024 float4 (16 KB)

    const int tid = threadIdx.x;
    const int tx = tid & 15, ty = tid >> 4;
    const int bh = blockIdx.y;
    const int q0 = blockIdx.x * 64;

    const int*    selp = g_sel + bh * SEL_STRIDE;
    const float4* kb4  = (const float4*)(k + (size_t)bh * S_ * D_);
    const float4* vb4  = (const float4*)(v + (size_t)bh * S_ * D_);
    const float4* qg4  = (const float4*)q;

    // gather + transpose selected Q rows into Qt[d][row]
    for (int lin = tid; lin < 1024; lin += 256) {
        int row = lin >> 4, dv = lin & 15;
        int qi = q0 + row;
        float4 vq = make_float4(0.f, 0.f, 0.f, 0.f);
        if (qi < u) vq = qg4[((size_t)bh * T_ + selp[qi]) * 16 + dv];
        float* dst = Qt + (4 * dv) * QSTRIDE_A + row;
        dst[0 * QSTRIDE_A] = vq.x;
        dst[1 * QSTRIDE_A] = vq.y;
        dst[2 * QSTRIDE_A] = vq.z;
        dst[3 * QSTRIDE_A] = vq.w;
    }

    float row_m[4], row_Z[4];
    unsigned long long Oxy[4], Ozw[4];
#pragma unroll
    for (int i = 0; i < 4; i++) {
        row_m[i] = -1e30f; row_Z[i] = 0.f;
        Oxy[i] = 0ULL; Ozw[i] = 0ULL;
    }

    for (int kt = 0; kt < S_ / 64; kt++) {
        __syncthreads();
        const float4* kp4 = kb4 + (size_t)kt * 64 * 16;
        const float4* vp4 = vb4 + (size_t)kt * 64 * 16;
        for (int lin = tid; lin < 1024; lin += 256) {
            int r = lin >> 4, dv = lin & 15;
            KP4[(r << 4) + (dv ^ (r & 15))] = kp4[lin];
            Vs4[lin] = vp4[lin];
        }
        __syncthreads();

        unsigned long long acc2[2][4];   // row-pairs (4ty+2p, 4ty+2p+1) x 4 cols
#pragma unroll
        for (int p = 0; p < 2; p++)
#pragma unroll
            for (int j = 0; j < 4; j++) acc2[p][j] = 0ULL;

#pragma unroll 4
        for (int dv = 0; dv < 16; dv++) {
            const float4* Kbase = KP4 + (tx << 4) + (dv ^ tx);
            float4 kv[4];
#pragma unroll
            for (int j = 0; j < 4; j++) kv[j] = Kbase[j << 8];

            const float* Qb = Qt + (4 * dv) * QSTRIDE_A + 4 * ty;
#pragma unroll
            for (int dsub = 0; dsub < 4; dsub++) {
                float4 qa = *(const float4*)(Qb + dsub * QSTRIDE_A);
                unsigned long long q01 = pack2(qa.x, qa.y);
                unsigned long long q23 = pack2(qa.z, qa.w);
#pragma unroll
                for (int j = 0; j < 4; j++) {
                    float ks = ((const float*)&kv[j])[dsub];
                    unsigned long long kb2 = pack2(ks, ks);
                    ffma2(acc2[0][j], q01, kb2);
                    ffma2(acc2[1][j], q23, kb2);
                }
            }
        }

        float p[4][4];
#pragma unroll
        for (int i = 0; i < 4; i++) {
            const int pp = i >> 1;
            float sv[4];
#pragma unroll
            for (int j = 0; j < 4; j++) {
                float2 uu = unpack2(acc2[pp][j]);
                sv[j] = (i & 1) ? uu.y : uu.x;
            }
            float tmax = -1e30f;
#pragma unroll
            for (int j = 0; j < 4; j++) {
                float s = fminf(fmaxf(sv[j] * SCALE, -50.f), 50.f);
                sv[j] = s;
                tmax = fmaxf(tmax, s);
            }
#pragma unroll
            for (int o = 8; o >= 1; o >>= 1)
                tmax = fmaxf(tmax, __shfl_xor_sync(0xffffffffu, tmax, o));

            float newm = fmaxf(row_m[i], tmax);
            float f = __expf(row_m[i] - newm);
            float zt = 0.f;
#pragma unroll
            for (int j = 0; j < 4; j++) {
                float e = __expf(sv[j] - newm);
                p[i][j] = e;
                zt += e;
            }
#pragma unroll
            for (int o = 8; o >= 1; o >>= 1)
                zt += __shfl_xor_sync(0xffffffffu, zt, o);

            row_Z[i] = row_Z[i] * f + zt;
            unsigned long long f2 = pack2(f, f);
            asm("mul.rn.f32x2 %0, %0, %1;" : "+l"(Oxy[i]) : "l"(f2));
            asm("mul.rn.f32x2 %0, %0, %1;" : "+l"(Ozw[i]) : "l"(f2));
            row_m[i] = newm;
        }
        __syncthreads();   // done reading KP4 as K

        float* Pf = (float*)KP4;
#pragma unroll
        for (int i = 0; i < 4; i++)
#pragma unroll
            for (int j = 0; j < 4; j++)
                Pf[((4 * ty + i) << 6) + tx + 16 * j] = p[i][j];
        __syncthreads();

#pragma unroll 4
        for (int kkv = 0; kkv < 16; kkv++) {
            float4 pv[4], vv[4];
#pragma unroll
            for (int i = 0; i < 4; i++) pv[i] = KP4[((4 * ty + i) << 4) + kkv];
#pragma unroll
            for (int m = 0; m < 4; m++) vv[m] = Vs4[((4 * kkv + m) << 4) + tx];
#pragma unroll
            for (int m = 0; m < 4; m++) {
                unsigned long long vxy = pack2(vv[m].x, vv[m].y);
                unsigned long long vzw = pack2(vv[m].z, vv[m].w);
#pragma unroll
                for (int i = 0; i < 4; i++) {
                    float pb = ((const float*)&pv[i])[m];
                    unsigned long long pb2 = pack2(pb, pb);
                    ffma2(Oxy[i], pb2, vxy);
                    ffma2(Ozw[i], pb2, vzw);
                }
            }
        }
    }

#pragma unroll
    for (int i = 0; i < 4; i++) {
        int qi = q0 + 4 * ty + i;
        if (qi < u) {
            int t = selp[qi];
            float inv = 1.0f / row_Z[i];
            float2 oxy = unpack2(Oxy[i]);
            float2 ozw = unpack2(Ozw[i]);
            float4 o = make_float4(oxy.x * inv, oxy.y * inv,
                                   ozw.x * inv, ozw.y * inv);
            float4* op4 = (float4*)(out + ((size_t)bh * T_ + t) * D_);
            op4[tx] = o;
        }
    }
}

// ---------------------------------------------------------------------------
extern "C" void kernel_launch(void* const* d_in, const int* in_sizes, int n_in,
                              void* d_out, int out_size)
{
    (void)in_sizes; (void)n_in;
    const float* q = (const float*)d_in[0];
    const float* k = (const float*)d_in[1];
    const float* v = (const float*)d_in[2];
    float* out = (float*)d_out;

    const int kl_smem   = 64 * QSTRIDE * 4 + 2 * 2048 * 16 + 256 * 8;  // ~101 KB
    const int attn_smem = 64 * QSTRIDE_A * 4 + 2 * 1024 * 16;          // ~50 KB
    cudaFuncSetAttribute(kl_kernel, cudaFuncAttributeMaxDynamicSharedMemorySize,
                         kl_smem);
    cudaFuncSetAttribute(attn_kernel, cudaFuncAttributeMaxDynamicSharedMemorySize,
                         attn_smem);

    cudaMemsetAsync(d_out, 0, (size_t)out_size * sizeof(float), 0);

    dim3 g1(T_ / 128, BH, 2);
    kl_kernel<<<g1, 256, kl_smem>>>(q, k);

    topk_kernel<<<BH, 256>>>(U_SEL);

    dim3 g3((U_SEL + 63) / 64, BH);
    attn_kernel<<<g3, 256, attn_smem>>>(q, k, v, out, U_SEL);
}